// round 5
// baseline (speedup 1.0000x reference)
#include <cuda_runtime.h>

// Haar DWT level-1 on channel 0 of x:(B=32, C=3, H=512, W=512) fp32.
// Output: (B, 4, 256, 256) fp32, order [ll, lh, hl, hh].
//
// Roofline: 67 MB compulsory L1<->L2 traffic against the ~6300 B/cyc
// chip-wide LTS cap => ~9.7us. Single-wave persistent grid (148 SMs x 8
// resident blocks x 256 threads, regs<=32) removes the wave transition +
// drain that the multi-wave variants pay.

#define H_IN 512
#define W_IN 512
#define H_OUT 256
#define W_OUT 256
#define C_IN 3

__device__ __forceinline__ void haar2(float a, float b, float c, float d,
                                      float& ll, float& lh, float& hl, float& hh) {
    float apb = a + b, cpd = c + d;
    float amb = a - b, cmd = c - d;
    ll = (apb + cpd) * 0.5f;
    lh = (apb - cpd) * 0.5f;
    hl = (amb + cmd) * 0.5f;
    hh = (amb - cmd) * 0.5f;
}

__global__ void __launch_bounds__(256, 8)
haar_dwt_kernel(const float* __restrict__ x, float* __restrict__ out) {
    const int JQ = W_OUT / 4;                       // 64 column-quads per row
    const int TOTAL = 32 * H_OUT * JQ;              // 524,288 quad-tasks
    const int stride = gridDim.x * blockDim.x;

    for (int idx = blockIdx.x * blockDim.x + threadIdx.x; idx < TOTAL; idx += stride) {
        int jq = idx % JQ;
        int i  = (idx / JQ) % H_OUT;
        int b  = idx / (JQ * H_OUT);

        const float* xp = x + (size_t)b * C_IN * H_IN * W_IN;
        int col = jq * 8;                           // 8 input columns
        const float* top = xp + (size_t)(2 * i)     * W_IN + col;
        const float* bot = xp + (size_t)(2 * i + 1) * W_IN + col;

        // 4 independent 16B loads
        const float4 t0 = *reinterpret_cast<const float4*>(top);
        const float4 t1 = *reinterpret_cast<const float4*>(top + 4);
        const float4 b0 = *reinterpret_cast<const float4*>(bot);
        const float4 b1 = *reinterpret_cast<const float4*>(bot + 4);

        float4 ll, lh, hl, hh;
        haar2(t0.x, t0.y, b0.x, b0.y, ll.x, lh.x, hl.x, hh.x);
        haar2(t0.z, t0.w, b0.z, b0.w, ll.y, lh.y, hl.y, hh.y);
        haar2(t1.x, t1.y, b1.x, b1.y, ll.z, lh.z, hl.z, hh.z);
        haar2(t1.z, t1.w, b1.z, b1.w, ll.w, lh.w, hl.w, hh.w);

        const size_t plane = (size_t)H_OUT * W_OUT;          // 65536
        float* op = out + (size_t)b * 4 * plane + (size_t)i * W_OUT + 4 * jq;
        *reinterpret_cast<float4*>(op + 0 * plane) = ll;
        *reinterpret_cast<float4*>(op + 1 * plane) = lh;
        *reinterpret_cast<float4*>(op + 2 * plane) = hl;
        *reinterpret_cast<float4*>(op + 3 * plane) = hh;
    }
}

extern "C" void kernel_launch(void* const* d_in, const int* in_sizes, int n_in,
                              void* d_out, int out_size) {
    const float* x = (const float*)d_in[0];
    float* out = (float*)d_out;

    // Single-wave persistent grid: 148 SMs x 8 blocks resident (occ 100% at
    // 256 thr / <=32 regs). Grid-stride covers the 524,288 tasks (~1.73 iters).
    const int blocks = 148 * 8;   // 1184
    const int threads = 256;
    haar_dwt_kernel<<<blocks, threads>>>(x, out);
}